// round 13
// baseline (speedup 1.0000x reference)
#include <cuda_runtime.h>

#define SQ   512
#define BB   64
#define HH   512
#define NB   128
#define NT   256
#define SPP  68        // partial-buffer batch stride (floats)

typedef unsigned long long ull;

// Static device scratch (allocation-guard safe)
__device__ float g_c[(long long)SQ * BB * HH];   // fallback c-state history
__device__ int   g_flag[SQ * NB];                // per (step, block) ready flags

// ---------------- PTX helpers ----------------
__device__ __forceinline__ void ffma2(ull& d, ull a, ull b) {
    asm("fma.rn.f32x2 %0, %1, %2, %0;" : "+l"(d) : "l"(a), "l"(b));
}
__device__ __forceinline__ ull addf2(ull a, ull b) {
    ull d; asm("add.rn.f32x2 %0, %1, %2;" : "=l"(d) : "l"(a), "l"(b)); return d;
}
__device__ __forceinline__ float2 unpackf2(ull v) {
    float2 r; asm("mov.b64 {%0, %1}, %2;" : "=f"(r.x), "=f"(r.y) : "l"(v)); return r;
}
__device__ __forceinline__ int ld_acq(const int* p) {
    int v; asm volatile("ld.acquire.gpu.global.s32 %0, [%1];" : "=r"(v) : "l"(p) : "memory");
    return v;
}
__device__ __forceinline__ void st_rel(int* p, int v) {
    asm volatile("st.release.gpu.global.s32 [%0], %1;" :: "l"(p), "r"(v) : "memory");
}
__device__ __forceinline__ void barn(int id) {
    asm volatile("bar.sync %0, 128;" :: "r"(id) : "memory");
}
__device__ __forceinline__ float fex2(float x) {
    float r; asm("ex2.approx.ftz.f32 %0, %1;" : "=f"(r) : "f"(x)); return r;
}
__device__ __forceinline__ float frcp(float x) {
    float r; asm("rcp.approx.ftz.f32 %0, %1;" : "=f"(r) : "f"(x)); return r;
}
__device__ __forceinline__ float fsig(float x) {
    return frcp(1.0f + fex2(-1.4426950408889634f * x));
}
__device__ __forceinline__ float ftanh(float x) {
    return 1.0f - 2.0f * frcp(1.0f + fex2(2.8853900817779268f * x));
}

// ---------------------------------------------------------------------------
__global__ void flag_init() { g_flag[blockIdx.x * NB + threadIdx.x] = 0; }

// ---------------------------------------------------------------------------
// smem: sX[32][512] (x half-batch) | sH[32][512] (h half-batch)
//       sP0/sP1 (x partials, double) | sPh (h partials): each [64][SPP]
// ---------------------------------------------------------------------------
#define SMEM_FLOATS (16384 + 16384 + 3 * 64 * SPP)   // 45824
#define SMEM_BYTES  (SMEM_FLOATS * 4)                // 183296

// One group's half-step work: stage 32 batches of its 512-k input slice into
// smem, then matvec them against the register-resident weights.
// Warp layout: lane l: r=l&15 (gate-row 0..15), kh=l>>4 (k-chunk half).
// Thread's k-slice: kbase = (gw*2+kh)*64, 64 floats (in 32 ull weight regs).
__device__ __forceinline__ void group_step(
    float* sIn, const float* __restrict__ gsrc, float* __restrict__ sP,
    const ull* wreg, int lt, int gw, int r, int kh, int kbase, int barid)
{
    #pragma unroll
    for (int half = 0; half < 2; half++) {
        // ---- stage 32 batches (64KB), coalesced float4 ----
        const float* gs = gsrc + half * 32 * HH;
        #pragma unroll 4
        for (int i = 0; i < 32; i++) {
            int s  = lt + (i << 7);        // 0..4095 float4 units
            int b  = s >> 7;
            int k4 = (s & 127) * 4;
            *(float4*)(sIn + b * HH + k4) = *(const float4*)(gs + b * HH + k4);
        }
        barn(barid);

        // ---- matvec: 32 batches x (16 rows x 64 k per thread) ----
        for (int bb = 0; bb < 32; bb++) {
            const float* ip = sIn + bb * HH + kbase;
            ull a0 = 0, a1 = 0, a2 = 0, a3 = 0;
            #pragma unroll
            for (int j = 0; j < 16; j += 2) {
                ulonglong2 iv0 = *(const ulonglong2*)(ip + j * 4);
                ulonglong2 iv1 = *(const ulonglong2*)(ip + j * 4 + 4);
                ffma2(a0, iv0.x, wreg[2 * j]);
                ffma2(a1, iv0.y, wreg[2 * j + 1]);
                ffma2(a2, iv1.x, wreg[2 * j + 2]);
                ffma2(a3, iv1.y, wreg[2 * j + 3]);
            }
            ull sT = addf2(addf2(a0, a1), addf2(a2, a3));
            float2 v = unpackf2(sT);
            float tot = v.x + v.y;
            tot += __shfl_xor_sync(0xffffffffu, tot, 16);   // fold k-halves
            if (kh == 0)
                sP[(half * 32 + bb) * SPP + r * 4 + gw] = tot;
        }
        if (half == 0) barn(barid);   // computed before restaging sIn
    }
}

// ---------------------------------------------------------------------------
// Persistent fused LSTM, weight-stationary registers.
// Warps 0-3: x-group (w_ih vs seq[t]); warps 4-7: h-group (w_hh vs h[t-1]).
// Each SMSP hosts one x-warp + one h-warp: x compute fills h's wait bubbles.
// h-group does the gate epilogue (c-state in its registers) and publishes.
// ---------------------------------------------------------------------------
__global__ __launch_bounds__(NT, 1)
void lstm_ws(const float* __restrict__ seq,
             const float* __restrict__ wih,
             const float* __restrict__ whh,
             const float* __restrict__ bih,
             const float* __restrict__ bhh,
             float* __restrict__ hout,    // [S][B][H]  hs output + h history
             float* __restrict__ cout)    // [S][B][H]  cs output
{
    extern __shared__ __align__(16) float sm[];
    float* sX  = sm;
    float* sH  = sm + 16384;
    float* sP0 = sm + 32768;             // x partials (even t)
    float* sP1 = sP0 + 64 * SPP;         // x partials (odd t)
    float* sPh = sP1 + 64 * SPP;         // h partials

    const int tid = threadIdx.x;
    const int isx = (tid < 128);
    const int lt  = tid & 127;
    const int gw  = (tid >> 5) & 3;
    const int l   = tid & 31;
    const int r   = l & 15;
    const int kh  = l >> 4;
    const int kbase = (gw * 2 + kh) * 64;
    const int n0  = blockIdx.x * 4;
    const int bid = blockIdx.x;

    // ---- load this thread's 64 weights into registers ----
    ull wreg[32];
    {
        const float* W  = isx ? wih : whh;
        const float* wp = W + (size_t)((r >> 2) * HH + n0 + (r & 3)) * HH + kbase;
        #pragma unroll
        for (int j = 0; j < 16; j++) {
            ulonglong2 v = *(const ulonglong2*)(wp + j * 4);
            wreg[2 * j] = v.x; wreg[2 * j + 1] = v.y;
        }
    }

    if (isx) {
        // =================== x-group ===================
        for (int t = 0; t < SQ; t++) {
            group_step(sX, seq + (size_t)t * BB * HH,
                       (t & 1) ? sP1 : sP0, wreg, lt, gw, r, kh, kbase, 1);
            __syncthreads();   // rendezvous: x-partials(t) published to h-group
        }
    } else {
        // =================== h-group ===================
        float bias[16];
        #pragma unroll
        for (int rr = 0; rr < 16; rr++)
            bias[rr] = bih[(rr >> 2) * HH + n0 + (rr & 3)]
                     + bhh[(rr >> 2) * HH + n0 + (rr & 3)];

        float cr[4] = {0.f, 0.f, 0.f, 0.f};   // c-state for batch lt>>1
        const int eb   = lt >> 1;             // epilogue batch
        const int role = lt & 1;              // 0: store h, 1: store c

        for (int t = 0; t < SQ; t++) {
            if (t > 0) {
                // wait for step t-1 from all 128 blocks (one flag per thread)
                while (ld_acq(&g_flag[(t - 1) * NB + lt]) == 0) {}
                barn(2);
                group_step(sH, hout + (size_t)(t - 1) * BB * HH,
                           sPh, wreg, lt, gw, r, kh, kbase, 2);
            }
            __syncthreads();   // x-partials(t) and h-partials(t) both ready

            // ---- gate epilogue for batch eb (all 4 columns) ----
            const float* px = ((t & 1) ? sP1 : sP0) + eb * SPP;
            const float* ph = sPh + eb * SPP;
            float pre[16];
            #pragma unroll
            for (int rr = 0; rr < 16; rr++) {
                float4 vx = *(const float4*)(px + rr * 4);
                float s = vx.x + vx.y + vx.z + vx.w;
                if (t > 0) {
                    float4 vh = *(const float4*)(ph + rr * 4);
                    s += vh.x + vh.y + vh.z + vh.w;
                }
                pre[rr] = bias[rr] + s;
            }
            float hn[4];
            #pragma unroll
            for (int c = 0; c < 4; c++) {    // gate order: i, f, g, o
                float cn = fsig(pre[4 + c]) * cr[c]
                         + fsig(pre[c]) * ftanh(pre[8 + c]);
                hn[c] = fsig(pre[12 + c]) * ftanh(cn);
                cr[c] = cn;
            }
            size_t off = (size_t)t * BB * HH + (size_t)eb * HH + n0;
            if (role == 0)
                *(float4*)(hout + off) = make_float4(hn[0], hn[1], hn[2], hn[3]);
            else
                *(float4*)(cout + off) = make_float4(cr[0], cr[1], cr[2], cr[3]);

            // publish step t (named bar orders h-group's stores; release store)
            barn(2);
            if (lt == 0) st_rel(&g_flag[t * NB + bid], 1);
        }
    }
}

// ---------------------------------------------------------------------------
// Host
// ---------------------------------------------------------------------------
extern "C" void kernel_launch(void* const* d_in, const int* in_sizes, int n_in,
                              void* d_out, int out_size)
{
    const float* seq = (const float*)d_in[0];
    const float* wih = (const float*)d_in[1];
    const float* whh = (const float*)d_in[2];
    const float* bih = (const float*)d_in[3];
    const float* bhh = (const float*)d_in[4];
    float* out = (float*)d_out;

    float* cscr;
    cudaGetSymbolAddress((void**)&cscr, g_c);

    const size_t SBH = (size_t)SQ * BB * HH;
    float* cbase = ((size_t)out_size >= 2 * SBH) ? (out + SBH) : cscr;

    flag_init<<<SQ, NB>>>();

    cudaFuncSetAttribute(lstm_ws, cudaFuncAttributeMaxDynamicSharedMemorySize,
                         SMEM_BYTES);
    lstm_ws<<<NB, NT, SMEM_BYTES>>>(seq, wih, whh, bih, bhh, out, cbase);
}

// round 14
// speedup vs baseline: 2.4629x; 2.4629x over previous
#include <cuda_runtime.h>

#define SQ   512
#define BB   64
#define FIN  512
#define HH   512
#define G4   2048
#define NB   128
#define NT   256

typedef unsigned long long ull;

// Static device scratch (allocation-guard safe)
__device__ float g_xg[(long long)SQ * BB * G4];   // input-projection gates [S, B, 4H]
__device__ float g_c [(long long)SQ * BB * HH];   // fallback c-state history
__device__ int   g_flag[SQ * NB];                 // per (step, block) ready flags

// ---------------- PTX helpers ----------------
__device__ __forceinline__ void ffma2(ull& d, ull a, ull b) {
    asm("fma.rn.f32x2 %0, %1, %2, %0;" : "+l"(d) : "l"(a), "l"(b));
}
__device__ __forceinline__ ull packf2(float x, float y) {
    ull d; asm("mov.b64 %0, {%1, %2};" : "=l"(d) : "f"(x), "f"(y)); return d;
}
__device__ __forceinline__ float2 unpackf2(ull v) {
    float2 r; asm("mov.b64 {%0, %1}, %2;" : "=f"(r.x), "=f"(r.y) : "l"(v)); return r;
}
__device__ __forceinline__ int ld_acq(const int* p) {
    int v; asm volatile("ld.acquire.gpu.global.s32 %0, [%1];" : "=r"(v) : "l"(p) : "memory");
    return v;
}
__device__ __forceinline__ void st_rel(int* p, int v) {
    asm volatile("st.release.gpu.global.s32 [%0], %1;" :: "l"(p), "r"(v) : "memory");
}
__device__ __forceinline__ float fex2(float x) {
    float r; asm("ex2.approx.ftz.f32 %0, %1;" : "=f"(r) : "f"(x)); return r;
}
__device__ __forceinline__ float frcp(float x) {
    float r; asm("rcp.approx.ftz.f32 %0, %1;" : "=f"(r) : "f"(x)); return r;
}
__device__ __forceinline__ float fsig(float x) {
    return frcp(1.0f + fex2(-1.4426950408889634f * x));
}
__device__ __forceinline__ float ftanh(float x) {
    return 1.0f - 2.0f * frcp(1.0f + fex2(2.8853900817779268f * x));
}

// ---------------------------------------------------------------------------
__global__ void flag_init() { g_flag[blockIdx.x * NB + threadIdx.x] = 0; }

// ---------------------------------------------------------------------------
// Kernel A: XG = seq @ w_ih^T + (b_ih + b_hh). (Round-3 version, ~1.75ms.)
// ---------------------------------------------------------------------------
__global__ __launch_bounds__(256)
void gemm_in(const float* __restrict__ A, const float* __restrict__ W,
             const float* __restrict__ bih, const float* __restrict__ bhh,
             float* __restrict__ C)
{
    __shared__ __align__(16) float As[8][132];
    __shared__ __align__(16) float Bs[8][132];

    const int tid  = threadIdx.x;
    const int tx   = tid & 15;
    const int ty   = tid >> 4;
    const int m0   = blockIdx.y * 128;
    const int n0   = blockIdx.x * 128;
    const int lrow = tid >> 1;
    const int lk4  = (tid & 1) * 4;

    const float* Aptr = A + (size_t)(m0 + lrow) * FIN + lk4;
    const float* Wptr = W + (size_t)(n0 + lrow) * FIN + lk4;

    ull acc2[4][8];
    #pragma unroll
    for (int i = 0; i < 4; i++)
        #pragma unroll
        for (int j = 0; j < 8; j++) acc2[i][j] = 0ULL;

    float4 ra = *(const float4*)(Aptr);
    float4 rb = *(const float4*)(Wptr);

    for (int kb = 0; kb < 64; kb++) {
        As[lk4 + 0][lrow] = ra.x; As[lk4 + 1][lrow] = ra.y;
        As[lk4 + 2][lrow] = ra.z; As[lk4 + 3][lrow] = ra.w;
        Bs[lk4 + 0][lrow] = rb.x; Bs[lk4 + 1][lrow] = rb.y;
        Bs[lk4 + 2][lrow] = rb.z; Bs[lk4 + 3][lrow] = rb.w;
        __syncthreads();

        if (kb < 63) {
            ra = *(const float4*)(Aptr + (kb + 1) * 8);
            rb = *(const float4*)(Wptr + (kb + 1) * 8);
        }

        #pragma unroll
        for (int kk = 0; kk < 8; kk++) {
            ulonglong2 a01 = *(const ulonglong2*)&As[kk][ty * 8];
            ulonglong2 a23 = *(const ulonglong2*)&As[kk][ty * 8 + 4];
            ull av[4] = {a01.x, a01.y, a23.x, a23.y};
            float4 b0 = *(const float4*)&Bs[kk][tx * 8];
            float4 b1 = *(const float4*)&Bs[kk][tx * 8 + 4];
            ull rbk[8];
            rbk[0] = packf2(b0.x, b0.x); rbk[1] = packf2(b0.y, b0.y);
            rbk[2] = packf2(b0.z, b0.z); rbk[3] = packf2(b0.w, b0.w);
            rbk[4] = packf2(b1.x, b1.x); rbk[5] = packf2(b1.y, b1.y);
            rbk[6] = packf2(b1.z, b1.z); rbk[7] = packf2(b1.w, b1.w);
            #pragma unroll
            for (int i2 = 0; i2 < 4; i2++)
                #pragma unroll
                for (int j = 0; j < 8; j++)
                    ffma2(acc2[i2][j], av[i2], rbk[j]);
        }
        __syncthreads();
    }

    float bias[8];
    #pragma unroll
    for (int j = 0; j < 8; j++) {
        int n = n0 + tx * 8 + j;
        bias[j] = bih[n] + bhh[n];
    }
    #pragma unroll
    for (int i2 = 0; i2 < 4; i2++) {
        float r0[8], r1[8];
        #pragma unroll
        for (int j = 0; j < 8; j++) {
            float2 v = unpackf2(acc2[i2][j]);
            r0[j] = v.x + bias[j];
            r1[j] = v.y + bias[j];
        }
        int m = m0 + ty * 8 + 2 * i2;
        float* p0 = C + (size_t)m * G4 + n0 + tx * 8;
        float* p1 = p0 + G4;
        *(float4*)(p0)     = make_float4(r0[0], r0[1], r0[2], r0[3]);
        *(float4*)(p0 + 4) = make_float4(r0[4], r0[5], r0[6], r0[7]);
        *(float4*)(p1)     = make_float4(r1[0], r1[1], r1[2], r1[3]);
        *(float4*)(p1 + 4) = make_float4(r1[4], r1[5], r1[6], r1[7]);
    }
}

// ---------------------------------------------------------------------------
// Kernel B v4: crossbar-minimal persistent recurrence.
// 128 blocks; block owns 4 h-columns n0 = 4*bid (16 gate-rows of w_hh).
// tid: w = tid>>5 (batch group, 8 batches), lane l: ks = l>>2 (8 k-slices
// of 64), g = l&3 (gate). Thread tile: 8 batches x 4 rows (gate g, cols 0-3),
// 64 k. acc packed over k (32 ull).
//
// smem (strides in floats, all 16B-aligned):
//   sW[r][ks][kk]: r*552 + ks*68 + kk   (r = g*4 + col)
//   sH[b][ks][kk]: b*552 + ks*68 + kk
//   Per w-LDS.128: quads 8g + 17ks mod 32 -> injective -> conflict-free.
//   Per h-LDS.128: only ks varies (g broadcast) -> 128B -> 1 wavefront.
//   sP[b][r]: b*20 + r (partials, 5KB).
// K-slices reduced in-warp via shfl.bfly(4,8,16); epilogue: thread (b,col)
// owns its c-state register forever.
// ---------------------------------------------------------------------------
#define KSL   68
#define BSTR  552
#define SW_FLOATS (16 * BSTR)            // 8832
#define SH_FLOATS (64 * BSTR)            // 35328
#define SP_FLOATS (64 * 20)              // 1280
#define SMEM_FLOATS (SW_FLOATS + SH_FLOATS + SP_FLOATS)   // 45440
#define SMEM_BYTES  (SMEM_FLOATS * 4)                     // 181760

__global__ __launch_bounds__(NT, 1)
void lstm_persist(const float* __restrict__ xg,
                  const float* __restrict__ Whh,
                  float* __restrict__ hout,   // [S][B][H] hs output + h history
                  float* __restrict__ cout)   // [S][B][H] cs output
{
    extern __shared__ __align__(16) float sm[];
    float* sW = sm;
    float* sH = sm + SW_FLOATS;
    float* sP = sm + SW_FLOATS + SH_FLOATS;

    const int tid = threadIdx.x;
    const int w   = tid >> 5;
    const int l   = tid & 31;
    const int ks  = l >> 2;
    const int g   = l & 3;
    const int n0  = blockIdx.x * 4;
    const int bid = blockIdx.x;

    // ---- Stage the 16 w_hh rows once: row r = g*4 + col ----
    #pragma unroll
    for (int i = 0; i < 8; i++) {
        int s  = tid + NT * i;             // 0..2047 float4 units
        int r  = s >> 7;                   // 0..15
        int k4 = (s & 127) * 4;            // 0..508
        int gg = r >> 2, col = r & 3;
        float4 v = *(const float4*)(Whh + (size_t)(gg * HH + n0 + col) * HH + k4);
        *(float4*)(sW + r * BSTR + (k4 >> 6) * KSL + (k4 & 63)) = v;
    }
    __syncthreads();

    // Epilogue identity: thread owns (eb, ec) forever; c-state in register.
    const int eb = w * 8 + (l >> 2);      // batch 0..63
    const int ec = l & 3;                 // column 0..3
    float creg = 0.0f;

    const float* wbase = sW + g * 4 * BSTR + ks * KSL;
    const float* hbase = sH + w * 8 * BSTR + ks * KSL;

    for (int t = 0; t < SQ; t++) {
        // Prefetch xg[t] for the epilogue (independent of the flag).
        const float* xq = xg + (size_t)t * BB * G4 + (size_t)eb * G4 + n0 + ec;
        float x0 = xq[0], x1 = xq[512], x2 = xq[1024], x3 = xq[1536];

        float pre0 = x0, pre1 = x1, pre2 = x2, pre3 = x3;

        if (t > 0) {
            // Wait for all 128 blocks to publish step t-1 (one flag/thread).
            if (tid < NB) {
                while (ld_acq(&g_flag[(t - 1) * NB + tid]) == 0) {}
            }
            __syncthreads();

            // Stage h(t-1): 128KB, coalesced LDG.128 -> STS.128
            const float* hp = hout + (size_t)(t - 1) * BB * HH;
            #pragma unroll
            for (int i = 0; i < 32; i++) {
                int s  = tid + NT * i;           // 0..8191 float4 units
                int b  = s >> 7;
                int k4 = (s & 127) * 4;
                float4 v = *(const float4*)(hp + b * HH + k4);
                *(float4*)(sH + b * BSTR + (k4 >> 6) * KSL + (k4 & 63)) = v;
            }
            __syncthreads();

            // ---- Matvec: 8 batches x 4 rows x 64 k, packed over k ----
            ull acc[8][4];
            #pragma unroll
            for (int bb = 0; bb < 8; bb++)
                #pragma unroll
                for (int j = 0; j < 4; j++) acc[bb][j] = 0ULL;

            #pragma unroll
            for (int q = 0; q < 16; q++) {       // k-quad within slice
                ulonglong2 w0 = *(const ulonglong2*)(wbase + q * 4);
                ulonglong2 w1 = *(const ulonglong2*)(wbase + BSTR + q * 4);
                ulonglong2 w2 = *(const ulonglong2*)(wbase + 2 * BSTR + q * 4);
                ulonglong2 w3 = *(const ulonglong2*)(wbase + 3 * BSTR + q * 4);
                #pragma unroll
                for (int bb = 0; bb < 8; bb++) {
                    ulonglong2 hv = *(const ulonglong2*)(hbase + bb * BSTR + q * 4);
                    ffma2(acc[bb][0], hv.x, w0.x); ffma2(acc[bb][0], hv.y, w0.y);
                    ffma2(acc[bb][1], hv.x, w1.x); ffma2(acc[bb][1], hv.y, w1.y);
                    ffma2(acc[bb][2], hv.x, w2.x); ffma2(acc[bb][2], hv.y, w2.y);
                    ffma2(acc[bb][3], hv.x, w3.x); ffma2(acc[bb][3], hv.y, w3.y);
                }
            }

            // Collapse f32x2, butterfly-reduce over ks (lane bits 2..4)
            float s_[8][4];
            #pragma unroll
            for (int bb = 0; bb < 8; bb++)
                #pragma unroll
                for (int j = 0; j < 4; j++) {
                    float2 v = unpackf2(acc[bb][j]);
                    float x = v.x + v.y;
                    x += __shfl_xor_sync(0xffffffffu, x, 4);
                    x += __shfl_xor_sync(0xffffffffu, x, 8);
                    x += __shfl_xor_sync(0xffffffffu, x, 16);
                    s_[bb][j] = x;
                }

            // ks==0 lanes publish partials: sP[b][g*4 + j] (STS.128)
            if (ks == 0) {
                #pragma unroll
                for (int bb = 0; bb < 8; bb++)
                    *(float4*)(sP + (w * 8 + bb) * 20 + g * 4) =
                        make_float4(s_[bb][0], s_[bb][1], s_[bb][2], s_[bb][3]);
            }
            __syncthreads();

            // Gather this thread's 4 gate pre-activations (conflict-free)
            const float* pp = sP + eb * 20 + ec;
            pre0 += pp[0];
            pre1 += pp[4];
            pre2 += pp[8];
            pre3 += pp[12];
        }

        // ---- Gate epilogue (order i, f, g, o); bias already in xg ----
        float cn = fsig(pre1) * creg + fsig(pre0) * ftanh(pre2);
        float hn = fsig(pre3) * ftanh(cn);
        creg = cn;

        size_t off = (size_t)t * BB * HH + (size_t)eb * HH + n0 + ec;
        hout[off] = hn;
        cout[off] = cn;

        // Publish step t (bar orders stores; release store publishes)
        __syncthreads();
        if (tid == 0) st_rel(&g_flag[t * NB + bid], 1);
    }
}

// ---------------------------------------------------------------------------
// Host
// ---------------------------------------------------------------------------
extern "C" void kernel_launch(void* const* d_in, const int* in_sizes, int n_in,
                              void* d_out, int out_size)
{
    const float* seq = (const float*)d_in[0];
    const float* wih = (const float*)d_in[1];
    const float* whh = (const float*)d_in[2];
    const float* bih = (const float*)d_in[3];
    const float* bhh = (const float*)d_in[4];
    float* out = (float*)d_out;

    float *xgp, *cscr;
    cudaGetSymbolAddress((void**)&xgp, g_xg);
    cudaGetSymbolAddress((void**)&cscr, g_c);

    const size_t SBH = (size_t)SQ * BB * HH;
    float* cbase = ((size_t)out_size >= 2 * SBH) ? (out + SBH) : cscr;

    flag_init<<<SQ, NB>>>();

    dim3 gg(G4 / 128, (SQ * BB) / 128);            // (16, 256)
    gemm_in<<<gg, 256>>>(seq, wih, bih, bhh, xgp);

    cudaFuncSetAttribute(lstm_persist, cudaFuncAttributeMaxDynamicSharedMemorySize,
                         SMEM_BYTES);
    lstm_persist<<<NB, NT, SMEM_BYTES>>>(xgp, whh, out, cbase);
}